// round 2
// baseline (speedup 1.0000x reference)
#include <cuda_runtime.h>
#include <cuda_fp16.h>
#include <cstdint>

#define EPS 1e-5f

// ---------------- device globals (scratch; no allocations allowed) ----------------
// packed recurrent weights: [m][b][r][k=512][rowlocal=256] fp16
//   m=0: whh0 ; m=1: wih1+whh1
__device__ __half g_warr[2u * 16u * 8u * 512u * 256u];                 // 67.1 MB
__device__ float g_gi0[16u * 256u * 2048u];                            // 33.5 MB: wih0@x + bih0+bhh0
__device__ float g_bias0[16u * 2048u];
__device__ float g_bias1[16u * 2048u];
__device__ float g_h[16u * 512u];
__device__ float2 g_part[16u * 8u * 5u];                               // per (b, rank): 4 gate stats + c stats
__device__ unsigned g_cnt[16];
__device__ unsigned g_flag[16];

// monotonic group barrier among the 8 CTAs of group g.  g_cnt/g_flag zeroed by k0 each launch.
__device__ __forceinline__ void group_barrier(int g, unsigned target) {
    __syncthreads();
    if (threadIdx.x == 0) {
        __threadfence();
        unsigned v = atomicAdd(&g_cnt[g], 1u) + 1u;
        if (v == target * 8u) {
            __threadfence();
            atomicExch(&g_flag[g], target);
        } else {
            unsigned f;
            do {
                asm volatile("ld.volatile.global.u32 %0, [%1];" : "=r"(f) : "l"(&g_flag[g]));
            } while (f < target);
        }
    }
    __syncthreads();
}

// ---------------- K0: per-launch init (biases, barrier state) ----------------
__global__ void k0_init(const float* __restrict__ bih0, const float* __restrict__ bhh0,
                        const float* __restrict__ bih1, const float* __restrict__ bhh1) {
    int i = blockIdx.x * blockDim.x + threadIdx.x;   // 128*256 = 32768 = 16*2048
    g_bias0[i] = bih0[i] + bhh0[i];
    g_bias1[i] = bih1[i] + bhh1[i];
    if (i < 16) { g_cnt[i] = 0u; g_flag[i] = 0u; }
}

// ---------------- K1: pack/transpose recurrent weights to fp16 [k][row] ----------------
// grid (8 ktile, 8 rank, 32 = m*16+b), 256 threads; tile = 64 k x 256 rows
__global__ void k1_pack(const float* __restrict__ whh0, const float* __restrict__ wih1,
                        const float* __restrict__ whh1) {
    __shared__ __align__(16) __half sm[64 * 264];
    int kt = blockIdx.x, r = blockIdx.y;
    int mb = blockIdx.z; int m = mb >> 4, b = mb & 15;
    int tid = threadIdx.x;
    int grow = ((tid >> 6) << 9) + (r << 6) + (tid & 63);  // global gate-row for this rowlocal
    int k0 = kt * 64;
    const float* s0 = (m == 0 ? whh0 : wih1) + ((size_t)(b * 2048 + grow) * 512 + k0);
    const float* s1 = whh1 + ((size_t)(b * 2048 + grow) * 512 + k0);
#pragma unroll
    for (int q = 0; q < 16; q++) {
        float4 v = *(const float4*)(s0 + q * 4);
        if (m) {
            float4 u = *(const float4*)(s1 + q * 4);
            v.x += u.x; v.y += u.y; v.z += u.z; v.w += u.w;
        }
        sm[(q * 4 + 0) * 264 + tid] = __float2half(v.x);
        sm[(q * 4 + 1) * 264 + tid] = __float2half(v.y);
        sm[(q * 4 + 2) * 264 + tid] = __float2half(v.z);
        sm[(q * 4 + 3) * 264 + tid] = __float2half(v.w);
    }
    __syncthreads();
    __half* out = &g_warr[(((size_t)mb) * 8u + r) * 512u * 256u + (size_t)k0 * 256u];
    int kk = tid >> 2, rb = (tid & 3) * 64;
    const uint4* src = (const uint4*)(sm + kk * 264 + rb);
    uint4* dst = (uint4*)(out + kk * 256 + rb);
#pragma unroll
    for (int q = 0; q < 8; q++) dst[q] = src[q];
}

// ---------------- K2: precompute gi0[b][t][row] = wih0@x_t + bias0 ----------------
// grid (32 rowtile, 4 ttile, 16 b), 256 threads; C tile 64x64, K-chunk 16
__global__ void k2_gemm(const float* __restrict__ wih0, const float* __restrict__ x) {
    __shared__ float As[64][17];
    __shared__ float Bs[16][65];
    int rt = blockIdx.x, tt = blockIdx.y, b = blockIdx.z;
    int row0 = rt * 64, t0 = tt * 64;
    int tid = threadIdx.x;
    int lm = tid >> 2, kq = tid & 3;
    const float* Ap = wih0 + ((size_t)(b * 2048 + row0 + lm) * 512 + kq * 4);
    const float* Bp = x + ((size_t)(b * 256 + t0 + lm) * 512 + kq * 4);
    int ty = tid >> 4, tx = tid & 15;
    float C[4][4];
#pragma unroll
    for (int i = 0; i < 4; i++)
#pragma unroll
        for (int j = 0; j < 4; j++) C[i][j] = 0.f;

    for (int kc = 0; kc < 512; kc += 16) {
        float4 a4 = *(const float4*)(Ap + kc);
        float4 b4 = *(const float4*)(Bp + kc);
        As[lm][kq * 4 + 0] = a4.x; As[lm][kq * 4 + 1] = a4.y;
        As[lm][kq * 4 + 2] = a4.z; As[lm][kq * 4 + 3] = a4.w;
        Bs[kq * 4 + 0][lm] = b4.x; Bs[kq * 4 + 1][lm] = b4.y;
        Bs[kq * 4 + 2][lm] = b4.z; Bs[kq * 4 + 3][lm] = b4.w;
        __syncthreads();
#pragma unroll
        for (int kk = 0; kk < 16; kk++) {
            float a[4], bb[4];
#pragma unroll
            for (int i = 0; i < 4; i++) a[i] = As[ty * 4 + i][kk];
#pragma unroll
            for (int j = 0; j < 4; j++) bb[j] = Bs[kk][tx * 4 + j];
#pragma unroll
            for (int i = 0; i < 4; i++)
#pragma unroll
                for (int j = 0; j < 4; j++) C[i][j] += a[i] * bb[j];
        }
        __syncthreads();
    }
    float4 bias = *(const float4*)&g_bias0[b * 2048 + row0 + ty * 4];
#pragma unroll
    for (int j = 0; j < 4; j++) {
        float4 vo;
        vo.x = C[0][j] + bias.x; vo.y = C[1][j] + bias.y;
        vo.z = C[2][j] + bias.z; vo.w = C[3][j] + bias.w;
        *(float4*)&g_gi0[((size_t)(b * 256 + t0 + tx * 4 + j)) * 2048 + row0 + ty * 4] = vo;
    }
}

// ---------------- K3: persistent recurrent kernel ----------------
// 128 CTAs x 256 threads. group g = batch, rank r owns h[64r..64r+64) and its 256 gate rows.
__global__ void __launch_bounds__(256, 1)
k3_lstm(const float* __restrict__ ln_w, const float* __restrict__ ln_b, float* __restrict__ y) {
    __shared__ float h_s[512];
    __shared__ float red[8][256];
    __shared__ float gp[256];
    __shared__ float act_s[256];
    __shared__ float c_s[64];
    __shared__ float o_s[64];
    __shared__ float wpart[8][2];
    __shared__ float gw_s[2][64], gb_s[2][64];

    int bid = blockIdx.x;
    int g = bid >> 3, r = bid & 7;
    int tid = threadIdx.x, warp = tid >> 5, lane = tid & 31;
    int gate = tid >> 6, jl = tid & 63;

    h_s[tid] = 0.f; h_s[tid + 256] = 0.f;
    if (tid < 64) c_s[tid] = 0.f;
    if (tid < 128) {
        int l = tid >> 6, jj = tid & 63;
        gw_s[l][jj] = ln_w[l * 512 + r * 64 + jj];
        gb_s[l][jj] = ln_b[l * 512 + r * 64 + jj];
    }
    __syncthreads();

    unsigned bar = 0;

    for (int t = 0; t < 256; t++) {
        for (int l = 0; l < 2; l++) {
            // ---- matvec: 256 rows x K=512; warp w owns k-range [64w,64w+64) ----
            const __half* W = &g_warr[(((size_t)(l * 16 + g)) * 8u + r) * 512u * 256u];
            const uint4* Wp = (const uint4*)(W) + (size_t)warp * 2048 + lane;
            float acc[8];
#pragma unroll
            for (int i = 0; i < 8; i++) acc[i] = 0.f;
#pragma unroll 8
            for (int kk = 0; kk < 64; kk++) {
                uint4 w4 = __ldcg(Wp + (size_t)kk * 32);
                float hk = h_s[warp * 64 + kk];
                const __half2* hp = (const __half2*)&w4;
                float2 f0 = __half22float2(hp[0]);
                float2 f1 = __half22float2(hp[1]);
                float2 f2 = __half22float2(hp[2]);
                float2 f3 = __half22float2(hp[3]);
                acc[0] += hk * f0.x; acc[1] += hk * f0.y;
                acc[2] += hk * f1.x; acc[3] += hk * f1.y;
                acc[4] += hk * f2.x; acc[5] += hk * f2.y;
                acc[6] += hk * f3.x; acc[7] += hk * f3.y;
            }
            *(float4*)&red[warp][lane * 8]     = make_float4(acc[0], acc[1], acc[2], acc[3]);
            *(float4*)&red[warp][lane * 8 + 4] = make_float4(acc[4], acc[5], acc[6], acc[7]);
            __syncthreads();
            float v = 0.f;
#pragma unroll
            for (int w = 0; w < 8; w++) v += red[w][tid];
            int rowg = (gate << 9) + (r << 6) + jl;
            v += (l == 0) ? __ldcg(&g_gi0[((size_t)(g * 256 + t)) * 2048 + rowg])
                          : g_bias1[g * 2048 + rowg];
            gp[tid] = v;

            // ---- gate LN partial stats (this CTA's 64 values per gate; 2 warps per gate) ----
            float s = v, q = v * v;
#pragma unroll
            for (int o = 16; o > 0; o >>= 1) {
                s += __shfl_xor_sync(0xffffffffu, s, o);
                q += __shfl_xor_sync(0xffffffffu, q, o);
            }
            if (lane == 0) { wpart[warp][0] = s; wpart[warp][1] = q; }
            __syncthreads();
            if (tid < 4) {
                float2 p;
                p.x = wpart[2 * tid][0] + wpart[2 * tid + 1][0];
                p.y = wpart[2 * tid][1] + wpart[2 * tid + 1][1];
                __stcg(&g_part[(g * 8 + r) * 5 + tid], p);
                __threadfence();
            }
            group_barrier(g, ++bar);

            // ---- finalize LN per gate, activations ----
            float S = 0.f, Q = 0.f;
#pragma unroll
            for (int rr = 0; rr < 8; rr++) {
                float2 p = __ldcg(&g_part[(g * 8 + rr) * 5 + gate]);
                S += p.x; Q += p.y;
            }
            float mean = S * (1.f / 512.f);
            float var = Q * (1.f / 512.f) - mean * mean;
            float rstd = rsqrtf(var + EPS);
            float xn = (gp[tid] - mean) * rstd * gw_s[l][jl] + gb_s[l][jl];
            float a = (gate == 2) ? tanhf(xn) : (1.f / (1.f + __expf(-xn)));
            act_s[tid] = a;
            __syncthreads();

            // ---- c update (owner j-slice lives in threads 0..63 = warps 0,1) ----
            float cn = 0.f;
            if (tid < 64) {
                cn = act_s[64 + tid] * c_s[tid] + act_s[tid] * act_s[128 + tid];
                c_s[tid] = cn;
                o_s[tid] = act_s[192 + tid];
            }
            if (warp < 2) {
                float s2 = cn, q2 = cn * cn;
#pragma unroll
                for (int o = 16; o > 0; o >>= 1) {
                    s2 += __shfl_xor_sync(0xffffffffu, s2, o);
                    q2 += __shfl_xor_sync(0xffffffffu, q2, o);
                }
                if (lane == 0) { wpart[warp][0] = s2; wpart[warp][1] = q2; }
            }
            __syncthreads();
            if (tid == 0) {
                float2 p;
                p.x = wpart[0][0] + wpart[1][0];
                p.y = wpart[0][1] + wpart[1][1];
                __stcg(&g_part[(g * 8 + r) * 5 + 4], p);
                __threadfence();
            }
            group_barrier(g, ++bar);

            // ---- LN(c), h update, publish h ----
            S = 0.f; Q = 0.f;
#pragma unroll
            for (int rr = 0; rr < 8; rr++) {
                float2 p = __ldcg(&g_part[(g * 8 + rr) * 5 + 4]);
                S += p.x; Q += p.y;
            }
            mean = S * (1.f / 512.f);
            var = Q * (1.f / 512.f) - mean * mean;
            rstd = rsqrtf(var + EPS);
            if (tid < 64) {
                float hv = o_s[tid] * tanhf((c_s[tid] - mean) * rstd * gw_s[l][tid] + gb_s[l][tid]);
                __stcg(&g_h[g * 512 + r * 64 + tid], hv);
                if (l == 1) y[((size_t)(g * 256 + t)) * 512 + r * 64 + tid] = hv;
                __threadfence();
            }
            group_barrier(g, ++bar);

            // ---- refresh local h copy ----
            h_s[tid]       = __ldcg(&g_h[g * 512 + tid]);
            h_s[tid + 256] = __ldcg(&g_h[g * 512 + 256 + tid]);
            __syncthreads();
        }
    }
}

// ---------------- launcher ----------------
extern "C" void kernel_launch(void* const* d_in, const int* in_sizes, int n_in,
                              void* d_out, int out_size) {
    (void)in_sizes; (void)n_in; (void)out_size;
    const float* x    = (const float*)d_in[0];
    const float* wih0 = (const float*)d_in[1];
    const float* whh0 = (const float*)d_in[2];
    const float* bih0 = (const float*)d_in[3];
    const float* bhh0 = (const float*)d_in[4];
    const float* wih1 = (const float*)d_in[5];
    const float* whh1 = (const float*)d_in[6];
    const float* bih1 = (const float*)d_in[7];
    const float* bhh1 = (const float*)d_in[8];
    const float* ln_w = (const float*)d_in[9];
    const float* ln_b = (const float*)d_in[10];
    float* y = (float*)d_out;

    k0_init<<<128, 256>>>(bih0, bhh0, bih1, bhh1);
    k1_pack<<<dim3(8, 8, 32), 256>>>(whh0, wih1, whh1);
    k2_gemm<<<dim3(32, 4, 16), 256>>>(wih0, x);
    k3_lstm<<<128, 256>>>(ln_w, ln_b, y);
}